// round 13
// baseline (speedup 1.0000x reference)
#include <cuda_runtime.h>
#include <cuda_bf16.h>
#include <cstdint>

// ============================================================================
// EinFFT (sm_103) — HMMA bf16x3 GEMM (3-stage, 2 CTAs/SM)
//   + radix-4 paired-real fwd FFT + FUSED (ifft4 + hermitian pack + radix-4
//     inverse FFT) epilogue — g_Wc staging buffer eliminated.
// ============================================================================

#define B_DIM 8
#define N_DIM 4096
#define C_DIM 768
#define BS    192
#define NB    4
#define M_TOT (B_DIM * N_DIM)      // 32768
#define KS    384                  // stacked [re|im]
#define GK    768                  // stored K: [hi(384) | lo(384)]
#define KCH   18                   // K chunks of 64 (effective K = 1152)
#define LAMBDA 0.01f
#define INV128 (1.0f / 128.0f)

#define FFT_THREADS 1024
#define FFT_SMEM ((4 * N_DIM + 1376) * 8)        // float2: 128KB data + 11KB twiddle
#define STAGE_BYTES 32768                        // A 16KB + B 16KB per stage
#define NSTG 3
#define GEMM_SMEM (NSTG * STAGE_BYTES)           // 98304 -> 2 CTAs/SM

// -------- scratch (static device globals; no runtime allocation) ------------
static __device__ float          g_Fr [(size_t)B_DIM * N_DIM * C_DIM];
static __device__ float          g_Fi [(size_t)B_DIM * N_DIM * C_DIM];
static __device__ unsigned short g_Xb [(size_t)NB * M_TOT * GK];   // bf16 [hi|lo]
static __device__ unsigned short g_Hb [(size_t)NB * M_TOT * GK];   // bf16 [hi|lo]
static __device__ unsigned short g_W1b[(size_t)NB * KS * GK];      // Wt bf16 [hi|lo]
static __device__ unsigned short g_W2b[(size_t)NB * KS * GK];
static __device__ float          g_B1 [NB * KS];
static __device__ float          g_B2 [NB * KS];
static __device__ float          g_P  [(size_t)NB * M_TOT * KS];   // fp32 MLP out

// ============================================================================
// helpers (arch-neutral PTX only)
// ============================================================================
__device__ __forceinline__ uint32_t smem_u32(const void* p) {
    uint32_t a;
    asm("{ .reg .u64 t; cvta.to.shared.u64 t, %1; cvt.u32.u64 %0, t; }"
        : "=r"(a) : "l"(p));
    return a;
}
__device__ __forceinline__ uint32_t swz128(uint32_t off) {
    return off ^ ((off >> 3) & 0x70);
}
__device__ __forceinline__ void cp16(uint32_t s, const void* g) {
    asm volatile("cp.async.cg.shared.global [%0], [%1], 16;" :: "r"(s), "l"(g));
}
__device__ __forceinline__ void ldsm_x4(uint32_t* r, uint32_t addr) {
    asm volatile("ldmatrix.sync.aligned.m8n8.x4.shared.b16 {%0,%1,%2,%3}, [%4];"
        : "=r"(r[0]), "=r"(r[1]), "=r"(r[2]), "=r"(r[3]) : "r"(addr));
}
__device__ __forceinline__ void mma16816(float* c, const uint32_t* a,
                                         uint32_t b0, uint32_t b1) {
    asm volatile(
        "mma.sync.aligned.m16n8k16.row.col.f32.bf16.bf16.f32 "
        "{%0,%1,%2,%3}, {%4,%5,%6,%7}, {%8,%9}, {%0,%1,%2,%3};"
        : "+f"(c[0]), "+f"(c[1]), "+f"(c[2]), "+f"(c[3])
        : "r"(a[0]), "r"(a[1]), "r"(a[2]), "r"(a[3]), "r"(b0), "r"(b1));
}
__device__ __forceinline__ float2 cmul(float2 a, float2 b) {
    return make_float2(a.x * b.x - a.y * b.y, a.x * b.y + a.y * b.x);
}

// chunk c -> (A k-offset, W k-offset) — SEQUENTIAL grouping (R10 order; the
// interleaved variant regressed gemm<2> by 38% in R11).
// c in [0,6): hi*hi;  [6,12): a_hi*w_lo;  [12,18): a_lo*w_hi
__device__ __forceinline__ void chunk_offsets(int c, int& aoff, int& boff) {
    if (c < 6)       { aoff = c * 64;              boff = c * 64; }
    else if (c < 12) { aoff = (c - 6) * 64;        boff = 384 + (c - 6) * 64; }
    else             { aoff = 384 + (c - 12) * 64; boff = (c - 12) * 64; }
}

__device__ __forceinline__ void load_chunk(const unsigned short* __restrict__ A,
                                           const unsigned short* __restrict__ W,
                                           uint32_t sA, uint32_t sB,
                                           int aoff, int boff, int tid) {
    #pragma unroll
    for (int t = 0; t < 4; t++) {
        int idx = tid + t * 256;
        int r = idx >> 3, i = idx & 7;
        cp16(sA + swz128((uint32_t)(r * 128 + i * 16)),
             A + (size_t)r * GK + aoff + i * 8);
    }
    #pragma unroll
    for (int t = 0; t < 4; t++) {
        int idx = tid + t * 256;
        int r = idx >> 3, i = idx & 7;
        cp16(sB + swz128((uint32_t)(r * 128 + i * 16)),
             W + (size_t)r * GK + boff + i * 8);
    }
    asm volatile("cp.async.commit_group;" ::: "memory");
}

// base-4 digit reversal of a 12-bit index
__device__ __forceinline__ int rev4(unsigned n) {
    unsigned r2 = __brev(n) >> 20;
    return (int)(((r2 & 0x555u) << 1) | ((r2 >> 1) & 0x555u));
}

// ============================================================================
// Radix-4 FFT-4096 core: 4 complex columns (float2), 6 stages, twiddle table.
// ============================================================================
template <int DIR>   // -1 forward, +1 inverse
static __device__ __forceinline__ void fft4_core(float2* s, float2* tw, int tid) {
    {
        int off = 0, q = 1;
        #pragma unroll
        for (int st = 0; st < 6; st++) {
            for (int p = tid; p < q; p += FFT_THREADS) {
                float sn, cs;
                __sincosf(-6.283185307179586f * (float)p / (float)(4 * q), &sn, &cs);
                tw[off + p] = make_float2(cs, sn);
            }
            off += q; q <<= 2;
        }
    }
    __syncthreads();

    int off = 0, q = 1;
    #pragma unroll
    for (int st = 0; st < 6; st++) {
        for (int it = tid; it < 4 * (N_DIM / 4); it += FFT_THREADS) {
            const int col = it >> 10;
            const int j   = it & (N_DIM / 4 - 1);
            const int pos = j & (q - 1);
            float2* p0 = s + col * N_DIM + ((j - pos) << 2) + pos;

            float2 w1 = tw[off + pos];
            if (DIR > 0) w1.y = -w1.y;
            float2 w2 = cmul(w1, w1);
            float2 w3 = cmul(w2, w1);

            float2 a  = p0[0];
            float2 b  = cmul(p0[q],     w1);
            float2 c2 = cmul(p0[2 * q], w2);
            float2 d  = cmul(p0[3 * q], w3);

            float2 t0 = make_float2(a.x + c2.x, a.y + c2.y);
            float2 t1 = make_float2(a.x - c2.x, a.y - c2.y);
            float2 t2 = make_float2(b.x + d.x,  b.y + d.y);
            float2 t3 = make_float2(b.x - d.x,  b.y - d.y);
            float2 t3r = (DIR < 0) ? make_float2(t3.y, -t3.x)
                                   : make_float2(-t3.y, t3.x);

            p0[0]     = make_float2(t0.x + t2.x,  t0.y + t2.y);
            p0[q]     = make_float2(t1.x + t3r.x, t1.y + t3r.y);
            p0[2 * q] = make_float2(t0.x - t2.x,  t0.y - t2.y);
            p0[3 * q] = make_float2(t1.x - t3r.x, t1.y - t3r.y);
        }
        __syncthreads();
        off += q; q <<= 2;
    }
}

// ============================================================================
// K1: forward FFT-4096, paired-real (8 channels as 4 complex cols), radix-4.
// ============================================================================
__global__ __launch_bounds__(FFT_THREADS, 1) void fft_n_fwd(const float* __restrict__ x) {
    extern __shared__ float2 smc[];
    float2* tw = smc + 4 * N_DIM;
    const int b  = blockIdx.x / 96;
    const int c0 = (blockIdx.x % 96) * 8;
    const int tid = threadIdx.x;

    for (int n = tid; n < N_DIM; n += FFT_THREADS) {
        const float* row = &x[((size_t)(b * N_DIM + n)) * C_DIM + c0];
        float4 v0 = *(const float4*)row;
        float4 v1 = *(const float4*)(row + 4);
        int r = rev4((unsigned)n);
        smc[0 * N_DIM + r] = make_float2(v0.x, v0.y);
        smc[1 * N_DIM + r] = make_float2(v0.z, v0.w);
        smc[2 * N_DIM + r] = make_float2(v1.x, v1.y);
        smc[3 * N_DIM + r] = make_float2(v1.z, v1.w);
    }
    fft4_core<-1>(smc, tw, tid);

    for (int k = tid; k < N_DIM; k += FFT_THREADS) {
        const int kr = (N_DIM - k) & (N_DIM - 1);
        float fr[8], fi[8];
        #pragma unroll
        for (int t = 0; t < 4; t++) {
            float2 P = smc[t * N_DIM + k];
            float2 Q = smc[t * N_DIM + kr];
            fr[2 * t]     = 0.5f * (P.x + Q.x);
            fi[2 * t]     = 0.5f * (P.y - Q.y);
            fr[2 * t + 1] = 0.5f * (P.y + Q.y);
            fi[2 * t + 1] = 0.5f * (Q.x - P.x);
        }
        size_t o = ((size_t)(b * N_DIM + k)) * C_DIM + c0;
        *(float4*)&g_Fr[o]     = *(float4*)&fr[0];
        *(float4*)&g_Fr[o + 4] = *(float4*)&fr[4];
        *(float4*)&g_Fi[o]     = *(float4*)&fi[0];
        *(float4*)&g_Fi[o + 4] = *(float4*)&fi[4];
    }
}

// ============================================================================
// K2: FFT-4 along block axis + 1/128 scale, pack bf16 hi/lo GEMM rows.
// ============================================================================
__global__ void fft4_pack() {
    int idx = blockIdx.x * blockDim.x + threadIdx.x;
    if (idx >= M_TOT * BS) return;
    const int m = idx / BS;
    const int d = idx % BS;

    const size_t base = (size_t)m * C_DIM + d;
    float xr0 = g_Fr[base],          xi0 = g_Fi[base];
    float xr1 = g_Fr[base + BS],     xi1 = g_Fi[base + BS];
    float xr2 = g_Fr[base + 2 * BS], xi2 = g_Fi[base + 2 * BS];
    float xr3 = g_Fr[base + 3 * BS], xi3 = g_Fi[base + 3 * BS];

    float yr[4], yi[4];
    yr[0] = (xr0 + xr1 + xr2 + xr3) * INV128;  yi[0] = (xi0 + xi1 + xi2 + xi3) * INV128;
    yr[1] = (xr0 + xi1 - xr2 - xi3) * INV128;  yi[1] = (xi0 - xr1 - xi2 + xr3) * INV128;
    yr[2] = (xr0 - xr1 + xr2 - xr3) * INV128;  yi[2] = (xi0 - xi1 + xi2 - xi3) * INV128;
    yr[3] = (xr0 - xi1 - xr2 + xi3) * INV128;  yi[3] = (xi0 + xr1 - xi2 - xr3) * INV128;

    const size_t PLX = (size_t)M_TOT * GK;
    #pragma unroll
    for (int p = 0; p < 4; p++) {
        unsigned short* row = g_Xb + p * PLX + (size_t)m * GK;
        __nv_bfloat16 hr = __float2bfloat16(yr[p]);
        __nv_bfloat16 hi = __float2bfloat16(yi[p]);
        row[d]            = __bfloat16_as_ushort(hr);
        row[BS + d]       = __bfloat16_as_ushort(hi);
        row[KS + d]       = __bfloat16_as_ushort(__float2bfloat16(yr[p] - __bfloat162float(hr)));
        row[KS + BS + d]  = __bfloat16_as_ushort(__float2bfloat16(yi[p] - __bfloat162float(hi)));
    }
}

// ============================================================================
// K3: stacked weights, transposed + bf16 hi/lo.  Ws = [[Wr, Wi], [-Wi, Wr]]
// ============================================================================
__global__ void prep_weights(const float* __restrict__ w1, const float* __restrict__ b1,
                             const float* __restrict__ w2, const float* __restrict__ b2) {
    int idx = blockIdx.x * blockDim.x + threadIdx.x;
    if (idx < NB * KS * GK) {
        int k   = idx % GK;
        int n   = (idx / GK) % KS;
        int blk = idx / (GK * KS);
        int kk  = (k >= KS) ? k - KS : k;
        bool lohalf = (k >= KS);
        int dd = (kk < BS) ? kk : kk - BS;
        int cc = (n  < BS) ? n  : n  - BS;
        bool rlo = kk < BS, clo = n < BS;
        size_t ir = ((size_t)blk        * BS + dd) * BS + cc;
        size_t ii = ((size_t)(NB + blk) * BS + dd) * BS + cc;
        float v1, v2;
        if (rlo == clo) { v1 =  w1[ir]; v2 =  w2[ir]; }
        else if (rlo)   { v1 =  w1[ii]; v2 =  w2[ii]; }
        else            { v1 = -w1[ii]; v2 = -w2[ii]; }
        __nv_bfloat16 h1 = __float2bfloat16(v1);
        __nv_bfloat16 h2 = __float2bfloat16(v2);
        if (lohalf) {
            g_W1b[idx] = __bfloat16_as_ushort(__float2bfloat16(v1 - __bfloat162float(h1)));
            g_W2b[idx] = __bfloat16_as_ushort(__float2bfloat16(v2 - __bfloat162float(h2)));
        } else {
            g_W1b[idx] = __bfloat16_as_ushort(h1);
            g_W2b[idx] = __bfloat16_as_ushort(h2);
        }
    }
    if (idx < NB * KS) {
        int blk = idx / KS;
        int c   = idx % KS;
        size_t ib = (c < BS) ? ((size_t)blk * BS + c)
                             : ((size_t)(NB + blk) * BS + (c - BS));
        g_B1[idx] = b1[ib];
        g_B2[idx] = b2[ib];
    }
}

// ============================================================================
// K4/K5: HMMA bf16x3 GEMM. CTA 128x128, 8 warps (4x2), warp tile 32x64.
// 3-stage cp.async pipeline, 2 CTAs/SM.  (Exact R10 configuration.)
// ============================================================================
template <int LAYER>
__global__ __launch_bounds__(256, 2) void gemm_mma() {
    extern __shared__ __align__(1024) char smem_raw[];
    const uint32_t smem = smem_u32(smem_raw);
    const int tid    = threadIdx.x;
    const int wid    = tid >> 5;
    const int lane   = tid & 31;
    const int warp_m = wid & 3;
    const int warp_n = wid >> 2;
    const int n0     = blockIdx.x * 128;
    const int tile_m = blockIdx.y * 128;
    const int blk    = blockIdx.z;

    const unsigned short* A = (LAYER == 1 ? g_Xb : g_Hb)
                            + (size_t)blk * M_TOT * GK + (size_t)tile_m * GK;
    const unsigned short* W = (LAYER == 1 ? g_W1b : g_W2b)
                            + (size_t)blk * KS * GK + (size_t)n0 * GK;
    const float* bias       = (LAYER == 1 ? g_B1 : g_B2) + blk * KS;

    float acc[2][8][4];
    #pragma unroll
    for (int i = 0; i < 2; i++)
        #pragma unroll
        for (int j = 0; j < 8; j++)
            #pragma unroll
            for (int q = 0; q < 4; q++) acc[i][j][q] = 0.f;

    #pragma unroll
    for (int c = 0; c < 2; c++) {
        int ao, bo; chunk_offsets(c, ao, bo);
        uint32_t sA = smem + c * STAGE_BYTES;
        load_chunk(A, W, sA, sA + 16384, ao, bo, tid);
    }

    const uint32_t a_row = (uint32_t)(warp_m * 32 + (lane & 15));
    const uint32_t a_cb  = (uint32_t)((lane >> 4) * 16);
    const uint32_t b_row = (uint32_t)(warp_n * 64 + (lane & 7) + ((lane >> 4) * 8));
    const uint32_t b_cb  = (uint32_t)(((lane >> 3) & 1) * 16);

    for (int c = 0; c < KCH; c++) {
        if (c + 1 < KCH) asm volatile("cp.async.wait_group 1;" ::: "memory");
        else             asm volatile("cp.async.wait_group 0;" ::: "memory");
        __syncthreads();

        if (c + 2 < KCH) {
            int ao, bo; chunk_offsets(c + 2, ao, bo);
            uint32_t sL = smem + ((c + 2) % NSTG) * STAGE_BYTES;
            load_chunk(A, W, sL, sL + 16384, ao, bo, tid);
        }

        const uint32_t sA = smem + (c % NSTG) * STAGE_BYTES;
        const uint32_t sB = sA + 16384;

        #pragma unroll
        for (int k16 = 0; k16 < 4; k16++) {
            uint32_t af[2][4], bf[4][4];
            #pragma unroll
            for (int mi = 0; mi < 2; mi++)
                ldsm_x4(af[mi], sA + swz128((a_row + mi * 16) * 128 + k16 * 32 + a_cb));
            #pragma unroll
            for (int nj = 0; nj < 4; nj++)
                ldsm_x4(bf[nj], sB + swz128((b_row + nj * 16) * 128 + k16 * 32 + b_cb));
            #pragma unroll
            for (int mi = 0; mi < 2; mi++)
                #pragma unroll
                for (int nj = 0; nj < 4; nj++) {
                    mma16816(acc[mi][2 * nj],     af[mi], bf[nj][0], bf[nj][1]);
                    mma16816(acc[mi][2 * nj + 1], af[mi], bf[nj][2], bf[nj][3]);
                }
        }
    }

    // epilogue
    #pragma unroll
    for (int mi = 0; mi < 2; mi++) {
        #pragma unroll
        for (int na = 0; na < 8; na++) {
            const int col  = n0 + warp_n * 64 + na * 8 + 2 * (lane & 3);
            const int row0 = tile_m + warp_m * 32 + mi * 16 + (lane >> 2);
            const float b0 = bias[col], b1 = bias[col + 1];
            #pragma unroll
            for (int h = 0; h < 2; h++) {
                const int row = row0 + h * 8;
                float v0 = acc[mi][na][2 * h]     + b0;
                float v1 = acc[mi][na][2 * h + 1] + b1;
                if (LAYER == 1) {
                    v0 = fmaxf(v0, 0.f);
                    v1 = fmaxf(v1, 0.f);
                    __nv_bfloat16 h0 = __float2bfloat16(v0);
                    __nv_bfloat16 h1 = __float2bfloat16(v1);
                    ushort2 hs = make_ushort2(__bfloat16_as_ushort(h0),
                                              __bfloat16_as_ushort(h1));
                    ushort2 ls = make_ushort2(
                        __bfloat16_as_ushort(__float2bfloat16(v0 - __bfloat162float(h0))),
                        __bfloat16_as_ushort(__float2bfloat16(v1 - __bfloat162float(h1))));
                    unsigned short* rb = g_Hb + ((size_t)blk * M_TOT + row) * GK;
                    *(ushort2*)(rb + col)      = hs;
                    *(ushort2*)(rb + KS + col) = ls;
                } else {
                    v0 = (v0 > LAMBDA) ? v0 - LAMBDA
                                       : ((v0 < -LAMBDA) ? v0 + LAMBDA : 0.f);
                    v1 = (v1 > LAMBDA) ? v1 - LAMBDA
                                       : ((v1 < -LAMBDA) ? v1 + LAMBDA : 0.f);
                    *(float2*)(g_P + ((size_t)blk * M_TOT + row) * KS + col)
                        = make_float2(v0, v1);
                }
            }
        }
    }
}

// ============================================================================
// K6 (FUSED): inverse FFT-4 across blocks + hermitian channel-pair pack
//   + inverse FFT-4096 + real output.  CTA = (b, dp); its 4 FFT columns are
//   the 4 BLOCKS of channel pair (2dp, 2dp+1).  Reads g_P directly.
// ============================================================================
__global__ __launch_bounds__(FFT_THREADS, 1) void fft_inv_fused(float* __restrict__ out) {
    extern __shared__ float2 smc[];
    float2* tw = smc + 4 * N_DIM;
    const int b  = blockIdx.x / 96;
    const int dp = blockIdx.x % 96;
    const int d  = 2 * dp;
    const int tid = threadIdx.x;

    const size_t PL = (size_t)M_TOT * KS;

    // phase 1: for each pair (k, N-k), build W_j[k], W_j[N-k] for all 4 blocks
    for (int kpos = tid; kpos < 2049; kpos += FFT_THREADS) {
        const int m1 = b * N_DIM + kpos;
        const int m2 = b * N_DIM + ((N_DIM - kpos) & (N_DIM - 1));

        float z1r[4], z1i[4], z2r[4], z2i[4];
        #pragma unroll
        for (int rowsel = 0; rowsel < 2; rowsel++) {
            const int m = rowsel ? m2 : m1;
            float yrA[4], yiA[4], yrB[4], yiB[4];
            #pragma unroll
            for (int k2 = 0; k2 < 4; k2++) {
                const float* pp = g_P + k2 * PL + (size_t)m * KS;
                float2 re = *(const float2*)(pp + d);
                float2 im = *(const float2*)(pp + BS + d);
                yrA[k2] = re.x;  yrB[k2] = re.y;
                yiA[k2] = im.x;  yiB[k2] = im.y;
            }
            float zrA[4], ziA[4], zrB[4], ziB[4];
            zrA[0] = yrA[0] + yrA[1] + yrA[2] + yrA[3];
            ziA[0] = yiA[0] + yiA[1] + yiA[2] + yiA[3];
            zrA[1] = yrA[0] - yiA[1] - yrA[2] + yiA[3];
            ziA[1] = yiA[0] + yrA[1] - yiA[2] - yrA[3];
            zrA[2] = yrA[0] - yrA[1] + yrA[2] - yrA[3];
            ziA[2] = yiA[0] - yiA[1] + yiA[2] - yiA[3];
            zrA[3] = yrA[0] + yiA[1] - yrA[2] - yiA[3];
            ziA[3] = yiA[0] - yrA[1] - yiA[2] + yrA[3];
            zrB[0] = yrB[0] + yrB[1] + yrB[2] + yrB[3];
            ziB[0] = yiB[0] + yiB[1] + yiB[2] + yiB[3];
            zrB[1] = yrB[0] - yiB[1] - yrB[2] + yiB[3];
            ziB[1] = yiB[0] + yrB[1] - yiB[2] - yrB[3];
            zrB[2] = yrB[0] - yrB[1] + yrB[2] - yrB[3];
            ziB[2] = yiB[0] - yiB[1] + yiB[2] - yiB[3];
            zrB[3] = yrB[0] + yiB[1] - yrB[2] - yiB[3];
            ziB[3] = yiB[0] - yrB[1] - yiB[2] + yrB[3];
            if (rowsel == 0) {
                #pragma unroll
                for (int j = 0; j < 4; j++) {
                    z1r[j] = zrA[j]; z1i[j] = ziA[j];
                    z2r[j] = zrB[j]; z2i[j] = ziB[j];
                }
            } else {
                const int r1 = rev4((unsigned)kpos);
                const int r2 = rev4((unsigned)((N_DIM - kpos) & (N_DIM - 1)));
                #pragma unroll
                for (int j = 0; j < 4; j++) {
                    float v1r = 0.5f * (z1r[j] + zrA[j]);
                    float v1i = 0.5f * (z1i[j] - ziA[j]);
                    float v2r = 0.5f * (z2r[j] + zrB[j]);
                    float v2i = 0.5f * (z2i[j] - ziB[j]);
                    smc[j * N_DIM + r1] = make_float2(v1r - v2i,  v1i + v2r);
                    smc[j * N_DIM + r2] = make_float2(v1r + v2i, -v1i + v2r);
                }
            }
        }
    }
    fft4_core<+1>(smc, tw, tid);

    // phase 2: write both real outputs per block column
    for (int n = tid; n < N_DIM; n += FFT_THREADS) {
        float* op = &out[((size_t)(b * N_DIM + n)) * C_DIM + d];
        #pragma unroll
        for (int j = 0; j < 4; j++) {
            float2 c = smc[j * N_DIM + n];
            *(float2*)(op + j * BS) = make_float2(c.x * INV128, c.y * INV128);
        }
    }
}

// ============================================================================
// launch
// ============================================================================
extern "C" void kernel_launch(void* const* d_in, const int* in_sizes, int n_in,
                              void* d_out, int out_size) {
    (void)in_sizes; (void)n_in; (void)out_size;
    const float* x  = (const float*)d_in[0];
    const float* w1 = (const float*)d_in[1];
    const float* b1 = (const float*)d_in[2];
    const float* w2 = (const float*)d_in[3];
    const float* b2 = (const float*)d_in[4];
    float* out = (float*)d_out;

    cudaFuncSetAttribute(fft_n_fwd,    cudaFuncAttributeMaxDynamicSharedMemorySize, FFT_SMEM);
    cudaFuncSetAttribute(fft_inv_fused, cudaFuncAttributeMaxDynamicSharedMemorySize, FFT_SMEM);
    cudaFuncSetAttribute(gemm_mma<1>,  cudaFuncAttributeMaxDynamicSharedMemorySize, GEMM_SMEM);
    cudaFuncSetAttribute(gemm_mma<2>,  cudaFuncAttributeMaxDynamicSharedMemorySize, GEMM_SMEM);

    fft_n_fwd<<<B_DIM * 96, FFT_THREADS, FFT_SMEM>>>(x);
    fft4_pack<<<(M_TOT * BS) / 256, 256>>>();
    prep_weights<<<(NB * KS * GK + 255) / 256, 256>>>(w1, b1, w2, b2);

    dim3 gg(3, M_TOT / 128, NB);
    gemm_mma<1><<<gg, 256, GEMM_SMEM>>>();
    gemm_mma<2><<<gg, 256, GEMM_SMEM>>>();

    fft_inv_fused<<<B_DIM * 96, FFT_THREADS, FFT_SMEM>>>(out);
}

// round 14
// speedup vs baseline: 1.5036x; 1.5036x over previous
#include <cuda_runtime.h>
#include <cuda_bf16.h>
#include <cstdint>

// ============================================================================
// EinFFT (sm_103) — HMMA bf16x3 GEMM (3-stage, 2 CTAs/SM)
//   + radix-4 paired-real fwd FFT + FUSED (ifft4 + hermitian pack + radix-4
//     inverse FFT) epilogue.
// RE-BENCH of R13: R13's uniform x1.55 slowdown on byte-identical GEMM code
// (tensor% flat, DRAM% and GB/s scaled by exactly 1/1.55) indicates an SM
// clock-domain drop, not a code regression. Identical source, clean measure.
// ============================================================================

#define B_DIM 8
#define N_DIM 4096
#define C_DIM 768
#define BS    192
#define NB    4
#define M_TOT (B_DIM * N_DIM)      // 32768
#define KS    384                  // stacked [re|im]
#define GK    768                  // stored K: [hi(384) | lo(384)]
#define KCH   18                   // K chunks of 64 (effective K = 1152)
#define LAMBDA 0.01f
#define INV128 (1.0f / 128.0f)

#define FFT_THREADS 1024
#define FFT_SMEM ((4 * N_DIM + 1376) * 8)        // float2: 128KB data + 11KB twiddle
#define STAGE_BYTES 32768                        // A 16KB + B 16KB per stage
#define NSTG 3
#define GEMM_SMEM (NSTG * STAGE_BYTES)           // 98304 -> 2 CTAs/SM

// -------- scratch (static device globals; no runtime allocation) ------------
static __device__ float          g_Fr [(size_t)B_DIM * N_DIM * C_DIM];
static __device__ float          g_Fi [(size_t)B_DIM * N_DIM * C_DIM];
static __device__ unsigned short g_Xb [(size_t)NB * M_TOT * GK];   // bf16 [hi|lo]
static __device__ unsigned short g_Hb [(size_t)NB * M_TOT * GK];   // bf16 [hi|lo]
static __device__ unsigned short g_W1b[(size_t)NB * KS * GK];      // Wt bf16 [hi|lo]
static __device__ unsigned short g_W2b[(size_t)NB * KS * GK];
static __device__ float          g_B1 [NB * KS];
static __device__ float          g_B2 [NB * KS];
static __device__ float          g_P  [(size_t)NB * M_TOT * KS];   // fp32 MLP out

// ============================================================================
// helpers (arch-neutral PTX only)
// ============================================================================
__device__ __forceinline__ uint32_t smem_u32(const void* p) {
    uint32_t a;
    asm("{ .reg .u64 t; cvta.to.shared.u64 t, %1; cvt.u32.u64 %0, t; }"
        : "=r"(a) : "l"(p));
    return a;
}
__device__ __forceinline__ uint32_t swz128(uint32_t off) {
    return off ^ ((off >> 3) & 0x70);
}
__device__ __forceinline__ void cp16(uint32_t s, const void* g) {
    asm volatile("cp.async.cg.shared.global [%0], [%1], 16;" :: "r"(s), "l"(g));
}
__device__ __forceinline__ void ldsm_x4(uint32_t* r, uint32_t addr) {
    asm volatile("ldmatrix.sync.aligned.m8n8.x4.shared.b16 {%0,%1,%2,%3}, [%4];"
        : "=r"(r[0]), "=r"(r[1]), "=r"(r[2]), "=r"(r[3]) : "r"(addr));
}
__device__ __forceinline__ void mma16816(float* c, const uint32_t* a,
                                         uint32_t b0, uint32_t b1) {
    asm volatile(
        "mma.sync.aligned.m16n8k16.row.col.f32.bf16.bf16.f32 "
        "{%0,%1,%2,%3}, {%4,%5,%6,%7}, {%8,%9}, {%0,%1,%2,%3};"
        : "+f"(c[0]), "+f"(c[1]), "+f"(c[2]), "+f"(c[3])
        : "r"(a[0]), "r"(a[1]), "r"(a[2]), "r"(a[3]), "r"(b0), "r"(b1));
}
__device__ __forceinline__ float2 cmul(float2 a, float2 b) {
    return make_float2(a.x * b.x - a.y * b.y, a.x * b.y + a.y * b.x);
}

// chunk c -> (A k-offset, W k-offset) — SEQUENTIAL grouping (R10 order).
// c in [0,6): hi*hi;  [6,12): a_hi*w_lo;  [12,18): a_lo*w_hi
__device__ __forceinline__ void chunk_offsets(int c, int& aoff, int& boff) {
    if (c < 6)       { aoff = c * 64;              boff = c * 64; }
    else if (c < 12) { aoff = (c - 6) * 64;        boff = 384 + (c - 6) * 64; }
    else             { aoff = 384 + (c - 12) * 64; boff = (c - 12) * 64; }
}

__device__ __forceinline__ void load_chunk(const unsigned short* __restrict__ A,
                                           const unsigned short* __restrict__ W,
                                           uint32_t sA, uint32_t sB,
                                           int aoff, int boff, int tid) {
    #pragma unroll
    for (int t = 0; t < 4; t++) {
        int idx = tid + t * 256;
        int r = idx >> 3, i = idx & 7;
        cp16(sA + swz128((uint32_t)(r * 128 + i * 16)),
             A + (size_t)r * GK + aoff + i * 8);
    }
    #pragma unroll
    for (int t = 0; t < 4; t++) {
        int idx = tid + t * 256;
        int r = idx >> 3, i = idx & 7;
        cp16(sB + swz128((uint32_t)(r * 128 + i * 16)),
             W + (size_t)r * GK + boff + i * 8);
    }
    asm volatile("cp.async.commit_group;" ::: "memory");
}

// base-4 digit reversal of a 12-bit index
__device__ __forceinline__ int rev4(unsigned n) {
    unsigned r2 = __brev(n) >> 20;
    return (int)(((r2 & 0x555u) << 1) | ((r2 >> 1) & 0x555u));
}

// ============================================================================
// Radix-4 FFT-4096 core: 4 complex columns (float2), 6 stages, twiddle table.
// ============================================================================
template <int DIR>   // -1 forward, +1 inverse
static __device__ __forceinline__ void fft4_core(float2* s, float2* tw, int tid) {
    {
        int off = 0, q = 1;
        #pragma unroll
        for (int st = 0; st < 6; st++) {
            for (int p = tid; p < q; p += FFT_THREADS) {
                float sn, cs;
                __sincosf(-6.283185307179586f * (float)p / (float)(4 * q), &sn, &cs);
                tw[off + p] = make_float2(cs, sn);
            }
            off += q; q <<= 2;
        }
    }
    __syncthreads();

    int off = 0, q = 1;
    #pragma unroll
    for (int st = 0; st < 6; st++) {
        for (int it = tid; it < 4 * (N_DIM / 4); it += FFT_THREADS) {
            const int col = it >> 10;
            const int j   = it & (N_DIM / 4 - 1);
            const int pos = j & (q - 1);
            float2* p0 = s + col * N_DIM + ((j - pos) << 2) + pos;

            float2 w1 = tw[off + pos];
            if (DIR > 0) w1.y = -w1.y;
            float2 w2 = cmul(w1, w1);
            float2 w3 = cmul(w2, w1);

            float2 a  = p0[0];
            float2 b  = cmul(p0[q],     w1);
            float2 c2 = cmul(p0[2 * q], w2);
            float2 d  = cmul(p0[3 * q], w3);

            float2 t0 = make_float2(a.x + c2.x, a.y + c2.y);
            float2 t1 = make_float2(a.x - c2.x, a.y - c2.y);
            float2 t2 = make_float2(b.x + d.x,  b.y + d.y);
            float2 t3 = make_float2(b.x - d.x,  b.y - d.y);
            float2 t3r = (DIR < 0) ? make_float2(t3.y, -t3.x)
                                   : make_float2(-t3.y, t3.x);

            p0[0]     = make_float2(t0.x + t2.x,  t0.y + t2.y);
            p0[q]     = make_float2(t1.x + t3r.x, t1.y + t3r.y);
            p0[2 * q] = make_float2(t0.x - t2.x,  t0.y - t2.y);
            p0[3 * q] = make_float2(t1.x - t3r.x, t1.y - t3r.y);
        }
        __syncthreads();
        off += q; q <<= 2;
    }
}

// ============================================================================
// K1: forward FFT-4096, paired-real (8 channels as 4 complex cols), radix-4.
// ============================================================================
__global__ __launch_bounds__(FFT_THREADS, 1) void fft_n_fwd(const float* __restrict__ x) {
    extern __shared__ float2 smc[];
    float2* tw = smc + 4 * N_DIM;
    const int b  = blockIdx.x / 96;
    const int c0 = (blockIdx.x % 96) * 8;
    const int tid = threadIdx.x;

    for (int n = tid; n < N_DIM; n += FFT_THREADS) {
        const float* row = &x[((size_t)(b * N_DIM + n)) * C_DIM + c0];
        float4 v0 = *(const float4*)row;
        float4 v1 = *(const float4*)(row + 4);
        int r = rev4((unsigned)n);
        smc[0 * N_DIM + r] = make_float2(v0.x, v0.y);
        smc[1 * N_DIM + r] = make_float2(v0.z, v0.w);
        smc[2 * N_DIM + r] = make_float2(v1.x, v1.y);
        smc[3 * N_DIM + r] = make_float2(v1.z, v1.w);
    }
    fft4_core<-1>(smc, tw, tid);

    for (int k = tid; k < N_DIM; k += FFT_THREADS) {
        const int kr = (N_DIM - k) & (N_DIM - 1);
        float fr[8], fi[8];
        #pragma unroll
        for (int t = 0; t < 4; t++) {
            float2 P = smc[t * N_DIM + k];
            float2 Q = smc[t * N_DIM + kr];
            fr[2 * t]     = 0.5f * (P.x + Q.x);
            fi[2 * t]     = 0.5f * (P.y - Q.y);
            fr[2 * t + 1] = 0.5f * (P.y + Q.y);
            fi[2 * t + 1] = 0.5f * (Q.x - P.x);
        }
        size_t o = ((size_t)(b * N_DIM + k)) * C_DIM + c0;
        *(float4*)&g_Fr[o]     = *(float4*)&fr[0];
        *(float4*)&g_Fr[o + 4] = *(float4*)&fr[4];
        *(float4*)&g_Fi[o]     = *(float4*)&fi[0];
        *(float4*)&g_Fi[o + 4] = *(float4*)&fi[4];
    }
}

// ============================================================================
// K2: FFT-4 along block axis + 1/128 scale, pack bf16 hi/lo GEMM rows.
// ============================================================================
__global__ void fft4_pack() {
    int idx = blockIdx.x * blockDim.x + threadIdx.x;
    if (idx >= M_TOT * BS) return;
    const int m = idx / BS;
    const int d = idx % BS;

    const size_t base = (size_t)m * C_DIM + d;
    float xr0 = g_Fr[base],          xi0 = g_Fi[base];
    float xr1 = g_Fr[base + BS],     xi1 = g_Fi[base + BS];
    float xr2 = g_Fr[base + 2 * BS], xi2 = g_Fi[base + 2 * BS];
    float xr3 = g_Fr[base + 3 * BS], xi3 = g_Fi[base + 3 * BS];

    float yr[4], yi[4];
    yr[0] = (xr0 + xr1 + xr2 + xr3) * INV128;  yi[0] = (xi0 + xi1 + xi2 + xi3) * INV128;
    yr[1] = (xr0 + xi1 - xr2 - xi3) * INV128;  yi[1] = (xi0 - xr1 - xi2 + xr3) * INV128;
    yr[2] = (xr0 - xr1 + xr2 - xr3) * INV128;  yi[2] = (xi0 - xi1 + xi2 - xi3) * INV128;
    yr[3] = (xr0 - xi1 - xr2 + xi3) * INV128;  yi[3] = (xi0 + xr1 - xi2 - xr3) * INV128;

    const size_t PLX = (size_t)M_TOT * GK;
    #pragma unroll
    for (int p = 0; p < 4; p++) {
        unsigned short* row = g_Xb + p * PLX + (size_t)m * GK;
        __nv_bfloat16 hr = __float2bfloat16(yr[p]);
        __nv_bfloat16 hi = __float2bfloat16(yi[p]);
        row[d]            = __bfloat16_as_ushort(hr);
        row[BS + d]       = __bfloat16_as_ushort(hi);
        row[KS + d]       = __bfloat16_as_ushort(__float2bfloat16(yr[p] - __bfloat162float(hr)));
        row[KS + BS + d]  = __bfloat16_as_ushort(__float2bfloat16(yi[p] - __bfloat162float(hi)));
    }
}

// ============================================================================
// K3: stacked weights, transposed + bf16 hi/lo.  Ws = [[Wr, Wi], [-Wi, Wr]]
// ============================================================================
__global__ void prep_weights(const float* __restrict__ w1, const float* __restrict__ b1,
                             const float* __restrict__ w2, const float* __restrict__ b2) {
    int idx = blockIdx.x * blockDim.x + threadIdx.x;
    if (idx < NB * KS * GK) {
        int k   = idx % GK;
        int n   = (idx / GK) % KS;
        int blk = idx / (GK * KS);
        int kk  = (k >= KS) ? k - KS : k;
        bool lohalf = (k >= KS);
        int dd = (kk < BS) ? kk : kk - BS;
        int cc = (n  < BS) ? n  : n  - BS;
        bool rlo = kk < BS, clo = n < BS;
        size_t ir = ((size_t)blk        * BS + dd) * BS + cc;
        size_t ii = ((size_t)(NB + blk) * BS + dd) * BS + cc;
        float v1, v2;
        if (rlo == clo) { v1 =  w1[ir]; v2 =  w2[ir]; }
        else if (rlo)   { v1 =  w1[ii]; v2 =  w2[ii]; }
        else            { v1 = -w1[ii]; v2 = -w2[ii]; }
        __nv_bfloat16 h1 = __float2bfloat16(v1);
        __nv_bfloat16 h2 = __float2bfloat16(v2);
        if (lohalf) {
            g_W1b[idx] = __bfloat16_as_ushort(__float2bfloat16(v1 - __bfloat162float(h1)));
            g_W2b[idx] = __bfloat16_as_ushort(__float2bfloat16(v2 - __bfloat162float(h2)));
        } else {
            g_W1b[idx] = __bfloat16_as_ushort(h1);
            g_W2b[idx] = __bfloat16_as_ushort(h2);
        }
    }
    if (idx < NB * KS) {
        int blk = idx / KS;
        int c   = idx % KS;
        size_t ib = (c < BS) ? ((size_t)blk * BS + c)
                             : ((size_t)(NB + blk) * BS + (c - BS));
        g_B1[idx] = b1[ib];
        g_B2[idx] = b2[ib];
    }
}

// ============================================================================
// K4/K5: HMMA bf16x3 GEMM. CTA 128x128, 8 warps (4x2), warp tile 32x64.
// 3-stage cp.async pipeline, 2 CTAs/SM.  (Exact R10 configuration.)
// ============================================================================
template <int LAYER>
__global__ __launch_bounds__(256, 2) void gemm_mma() {
    extern __shared__ __align__(1024) char smem_raw[];
    const uint32_t smem = smem_u32(smem_raw);
    const int tid    = threadIdx.x;
    const int wid    = tid >> 5;
    const int lane   = tid & 31;
    const int warp_m = wid & 3;
    const int warp_n = wid >> 2;
    const int n0     = blockIdx.x * 128;
    const int tile_m = blockIdx.y * 128;
    const int blk    = blockIdx.z;

    const unsigned short* A = (LAYER == 1 ? g_Xb : g_Hb)
                            + (size_t)blk * M_TOT * GK + (size_t)tile_m * GK;
    const unsigned short* W = (LAYER == 1 ? g_W1b : g_W2b)
                            + (size_t)blk * KS * GK + (size_t)n0 * GK;
    const float* bias       = (LAYER == 1 ? g_B1 : g_B2) + blk * KS;

    float acc[2][8][4];
    #pragma unroll
    for (int i = 0; i < 2; i++)
        #pragma unroll
        for (int j = 0; j < 8; j++)
            #pragma unroll
            for (int q = 0; q < 4; q++) acc[i][j][q] = 0.f;

    #pragma unroll
    for (int c = 0; c < 2; c++) {
        int ao, bo; chunk_offsets(c, ao, bo);
        uint32_t sA = smem + c * STAGE_BYTES;
        load_chunk(A, W, sA, sA + 16384, ao, bo, tid);
    }

    const uint32_t a_row = (uint32_t)(warp_m * 32 + (lane & 15));
    const uint32_t a_cb  = (uint32_t)((lane >> 4) * 16);
    const uint32_t b_row = (uint32_t)(warp_n * 64 + (lane & 7) + ((lane >> 4) * 8));
    const uint32_t b_cb  = (uint32_t)(((lane >> 3) & 1) * 16);

    for (int c = 0; c < KCH; c++) {
        if (c + 1 < KCH) asm volatile("cp.async.wait_group 1;" ::: "memory");
        else             asm volatile("cp.async.wait_group 0;" ::: "memory");
        __syncthreads();

        if (c + 2 < KCH) {
            int ao, bo; chunk_offsets(c + 2, ao, bo);
            uint32_t sL = smem + ((c + 2) % NSTG) * STAGE_BYTES;
            load_chunk(A, W, sL, sL + 16384, ao, bo, tid);
        }

        const uint32_t sA = smem + (c % NSTG) * STAGE_BYTES;
        const uint32_t sB = sA + 16384;

        #pragma unroll
        for (int k16 = 0; k16 < 4; k16++) {
            uint32_t af[2][4], bf[4][4];
            #pragma unroll
            for (int mi = 0; mi < 2; mi++)
                ldsm_x4(af[mi], sA + swz128((a_row + mi * 16) * 128 + k16 * 32 + a_cb));
            #pragma unroll
            for (int nj = 0; nj < 4; nj++)
                ldsm_x4(bf[nj], sB + swz128((b_row + nj * 16) * 128 + k16 * 32 + b_cb));
            #pragma unroll
            for (int mi = 0; mi < 2; mi++)
                #pragma unroll
                for (int nj = 0; nj < 4; nj++) {
                    mma16816(acc[mi][2 * nj],     af[mi], bf[nj][0], bf[nj][1]);
                    mma16816(acc[mi][2 * nj + 1], af[mi], bf[nj][2], bf[nj][3]);
                }
        }
    }

    // epilogue
    #pragma unroll
    for (int mi = 0; mi < 2; mi++) {
        #pragma unroll
        for (int na = 0; na < 8; na++) {
            const int col  = n0 + warp_n * 64 + na * 8 + 2 * (lane & 3);
            const int row0 = tile_m + warp_m * 32 + mi * 16 + (lane >> 2);
            const float b0 = bias[col], b1 = bias[col + 1];
            #pragma unroll
            for (int h = 0; h < 2; h++) {
                const int row = row0 + h * 8;
                float v0 = acc[mi][na][2 * h]     + b0;
                float v1 = acc[mi][na][2 * h + 1] + b1;
                if (LAYER == 1) {
                    v0 = fmaxf(v0, 0.f);
                    v1 = fmaxf(v1, 0.f);
                    __nv_bfloat16 h0 = __float2bfloat16(v0);
                    __nv_bfloat16 h1 = __float2bfloat16(v1);
                    ushort2 hs = make_ushort2(__bfloat16_as_ushort(h0),
                                              __bfloat16_as_ushort(h1));
                    ushort2 ls = make_ushort2(
                        __bfloat16_as_ushort(__float2bfloat16(v0 - __bfloat162float(h0))),
                        __bfloat16_as_ushort(__float2bfloat16(v1 - __bfloat162float(h1))));
                    unsigned short* rb = g_Hb + ((size_t)blk * M_TOT + row) * GK;
                    *(ushort2*)(rb + col)      = hs;
                    *(ushort2*)(rb + KS + col) = ls;
                } else {
                    v0 = (v0 > LAMBDA) ? v0 - LAMBDA
                                       : ((v0 < -LAMBDA) ? v0 + LAMBDA : 0.f);
                    v1 = (v1 > LAMBDA) ? v1 - LAMBDA
                                       : ((v1 < -LAMBDA) ? v1 + LAMBDA : 0.f);
                    *(float2*)(g_P + ((size_t)blk * M_TOT + row) * KS + col)
                        = make_float2(v0, v1);
                }
            }
        }
    }
}

// ============================================================================
// K6 (FUSED): inverse FFT-4 across blocks + hermitian channel-pair pack
//   + inverse FFT-4096 + real output.  CTA = (b, dp); its 4 FFT columns are
//   the 4 BLOCKS of channel pair (2dp, 2dp+1).  Reads g_P directly.
// ============================================================================
__global__ __launch_bounds__(FFT_THREADS, 1) void fft_inv_fused(float* __restrict__ out) {
    extern __shared__ float2 smc[];
    float2* tw = smc + 4 * N_DIM;
    const int b  = blockIdx.x / 96;
    const int dp = blockIdx.x % 96;
    const int d  = 2 * dp;
    const int tid = threadIdx.x;

    const size_t PL = (size_t)M_TOT * KS;

    // phase 1: for each pair (k, N-k), build W_j[k], W_j[N-k] for all 4 blocks
    for (int kpos = tid; kpos < 2049; kpos += FFT_THREADS) {
        const int m1 = b * N_DIM + kpos;
        const int m2 = b * N_DIM + ((N_DIM - kpos) & (N_DIM - 1));

        float z1r[4], z1i[4], z2r[4], z2i[4];
        #pragma unroll
        for (int rowsel = 0; rowsel < 2; rowsel++) {
            const int m = rowsel ? m2 : m1;
            float yrA[4], yiA[4], yrB[4], yiB[4];
            #pragma unroll
            for (int k2 = 0; k2 < 4; k2++) {
                const float* pp = g_P + k2 * PL + (size_t)m * KS;
                float2 re = *(const float2*)(pp + d);
                float2 im = *(const float2*)(pp + BS + d);
                yrA[k2] = re.x;  yrB[k2] = re.y;
                yiA[k2] = im.x;  yiB[k2] = im.y;
            }
            float zrA[4], ziA[4], zrB[4], ziB[4];
            zrA[0] = yrA[0] + yrA[1] + yrA[2] + yrA[3];
            ziA[0] = yiA[0] + yiA[1] + yiA[2] + yiA[3];
            zrA[1] = yrA[0] - yiA[1] - yrA[2] + yiA[3];
            ziA[1] = yiA[0] + yrA[1] - yiA[2] - yrA[3];
            zrA[2] = yrA[0] - yrA[1] + yrA[2] - yrA[3];
            ziA[2] = yiA[0] - yiA[1] + yiA[2] - yiA[3];
            zrA[3] = yrA[0] + yiA[1] - yrA[2] - yiA[3];
            ziA[3] = yiA[0] - yrA[1] - yiA[2] + yrA[3];
            zrB[0] = yrB[0] + yrB[1] + yrB[2] + yrB[3];
            ziB[0] = yiB[0] + yiB[1] + yiB[2] + yiB[3];
            zrB[1] = yrB[0] - yiB[1] - yrB[2] + yiB[3];
            ziB[1] = yiB[0] + yrB[1] - yiB[2] - yrB[3];
            zrB[2] = yrB[0] - yrB[1] + yrB[2] - yrB[3];
            ziB[2] = yiB[0] - yiB[1] + yiB[2] - yiB[3];
            zrB[3] = yrB[0] + yiB[1] - yrB[2] - yiB[3];
            ziB[3] = yiB[0] - yrB[1] - yiB[2] + yrB[3];
            if (rowsel == 0) {
                #pragma unroll
                for (int j = 0; j < 4; j++) {
                    z1r[j] = zrA[j]; z1i[j] = ziA[j];
                    z2r[j] = zrB[j]; z2i[j] = ziB[j];
                }
            } else {
                const int r1 = rev4((unsigned)kpos);
                const int r2 = rev4((unsigned)((N_DIM - kpos) & (N_DIM - 1)));
                #pragma unroll
                for (int j = 0; j < 4; j++) {
                    float v1r = 0.5f * (z1r[j] + zrA[j]);
                    float v1i = 0.5f * (z1i[j] - ziA[j]);
                    float v2r = 0.5f * (z2r[j] + zrB[j]);
                    float v2i = 0.5f * (z2i[j] - ziB[j]);
                    smc[j * N_DIM + r1] = make_float2(v1r - v2i,  v1i + v2r);
                    smc[j * N_DIM + r2] = make_float2(v1r + v2i, -v1i + v2r);
                }
            }
        }
    }
    fft4_core<+1>(smc, tw, tid);

    // phase 2: write both real outputs per block column
    for (int n = tid; n < N_DIM; n += FFT_THREADS) {
        float* op = &out[((size_t)(b * N_DIM + n)) * C_DIM + d];
        #pragma unroll
        for (int j = 0; j < 4; j++) {
            float2 c = smc[j * N_DIM + n];
            *(float2*)(op + j * BS) = make_float2(c.x * INV128, c.y * INV128);
        }
    }
}

// ============================================================================
// launch
// ============================================================================
extern "C" void kernel_launch(void* const* d_in, const int* in_sizes, int n_in,
                              void* d_out, int out_size) {
    (void)in_sizes; (void)n_in; (void)out_size;
    const float* x  = (const float*)d_in[0];
    const float* w1 = (const float*)d_in[1];
    const float* b1 = (const float*)d_in[2];
    const float* w2 = (const float*)d_in[3];
    const float* b2 = (const float*)d_in[4];
    float* out = (float*)d_out;

    cudaFuncSetAttribute(fft_n_fwd,     cudaFuncAttributeMaxDynamicSharedMemorySize, FFT_SMEM);
    cudaFuncSetAttribute(fft_inv_fused, cudaFuncAttributeMaxDynamicSharedMemorySize, FFT_SMEM);
    cudaFuncSetAttribute(gemm_mma<1>,   cudaFuncAttributeMaxDynamicSharedMemorySize, GEMM_SMEM);
    cudaFuncSetAttribute(gemm_mma<2>,   cudaFuncAttributeMaxDynamicSharedMemorySize, GEMM_SMEM);

    fft_n_fwd<<<B_DIM * 96, FFT_THREADS, FFT_SMEM>>>(x);
    fft4_pack<<<(M_TOT * BS) / 256, 256>>>();
    prep_weights<<<(NB * KS * GK + 255) / 256, 256>>>(w1, b1, w2, b2);

    dim3 gg(3, M_TOT / 128, NB);
    gemm_mma<1><<<gg, 256, GEMM_SMEM>>>();
    gemm_mma<2><<<gg, 256, GEMM_SMEM>>>();

    fft_inv_fused<<<B_DIM * 96, FFT_THREADS, FFT_SMEM>>>(out);
}

// round 17
// speedup vs baseline: 1.7578x; 1.1690x over previous
#include <cuda_runtime.h>
#include <cuda_bf16.h>
#include <cstdint>

// ============================================================================
// EinFFT (sm_103) — HMMA bf16x3 GEMM (3-stage, 2 CTAs/SM, R10 chunk order)
//   + FUSED fwd (radix-4 FFT + FFT4 + bf16 pack, K-major A, coalesced)
//   + split inverse (wpack -> g_Wc -> radix-4 inverse FFT)  [R14 clean-clock
//     A/B showed the fused inverse is ~90us slower: scattered g_P reads]
// ============================================================================

#define B_DIM 8
#define N_DIM 4096
#define C_DIM 768
#define BS    192
#define NB    4
#define M_TOT (B_DIM * N_DIM)      // 32768
#define KS    384                  // stacked [re|im]
#define GK    768                  // stored K: [hi(384) | lo(384)]
#define KCH   18                   // K chunks of 64 (effective K = 1152)
#define LAMBDA 0.01f
#define INV128 (1.0f / 128.0f)

#define FFT_THREADS 1024
#define FFT_SMEM ((4 * N_DIM + 1376) * 8)        // float2: 128KB data + 11KB twiddle
#define STAGE_BYTES 32768                        // A 16KB + B 16KB per stage
#define NSTG 3
#define GEMM_SMEM (NSTG * STAGE_BYTES)           // 98304 -> 2 CTAs/SM

// -------- scratch (static device globals; no runtime allocation) ------------
static __device__ unsigned short g_XbT[(size_t)NB * GK * M_TOT];   // bf16 K-MAJOR [blk][k][m]
static __device__ unsigned short g_Hb [(size_t)NB * M_TOT * GK];   // bf16 m-major [hi|lo]
static __device__ unsigned short g_W1b[(size_t)NB * KS * GK];      // Wt bf16 [hi|lo]
static __device__ unsigned short g_W2b[(size_t)NB * KS * GK];
static __device__ float          g_B1 [NB * KS];
static __device__ float          g_B2 [NB * KS];
static __device__ float          g_P  [(size_t)NB * M_TOT * KS];   // fp32 MLP out
static __device__ float2         g_Wc [(size_t)NB * M_TOT * 96];   // packed herm spectrum

// ============================================================================
// helpers (arch-neutral PTX only)
// ============================================================================
__device__ __forceinline__ uint32_t smem_u32(const void* p) {
    uint32_t a;
    asm("{ .reg .u64 t; cvta.to.shared.u64 t, %1; cvt.u32.u64 %0, t; }"
        : "=r"(a) : "l"(p));
    return a;
}
__device__ __forceinline__ uint32_t swz128(uint32_t off) {
    return off ^ ((off >> 3) & 0x70);
}
__device__ __forceinline__ void cp16(uint32_t s, const void* g) {
    asm volatile("cp.async.cg.shared.global [%0], [%1], 16;" :: "r"(s), "l"(g));
}
__device__ __forceinline__ void ldsm_x4(uint32_t* r, uint32_t addr) {
    asm volatile("ldmatrix.sync.aligned.m8n8.x4.shared.b16 {%0,%1,%2,%3}, [%4];"
        : "=r"(r[0]), "=r"(r[1]), "=r"(r[2]), "=r"(r[3]) : "r"(addr));
}
__device__ __forceinline__ void ldsm_x4_t(uint32_t* r, uint32_t addr) {
    asm volatile("ldmatrix.sync.aligned.m8n8.x4.trans.shared.b16 {%0,%1,%2,%3}, [%4];"
        : "=r"(r[0]), "=r"(r[1]), "=r"(r[2]), "=r"(r[3]) : "r"(addr));
}
__device__ __forceinline__ void mma16816(float* c, const uint32_t* a,
                                         uint32_t b0, uint32_t b1) {
    asm volatile(
        "mma.sync.aligned.m16n8k16.row.col.f32.bf16.bf16.f32 "
        "{%0,%1,%2,%3}, {%4,%5,%6,%7}, {%8,%9}, {%0,%1,%2,%3};"
        : "+f"(c[0]), "+f"(c[1]), "+f"(c[2]), "+f"(c[3])
        : "r"(a[0]), "r"(a[1]), "r"(a[2]), "r"(a[3]), "r"(b0), "r"(b1));
}
__device__ __forceinline__ float2 cmul(float2 a, float2 b) {
    return make_float2(a.x * b.x - a.y * b.y, a.x * b.y + a.y * b.x);
}

// chunk c -> (A k-offset, W k-offset) — SEQUENTIAL grouping (R10 order; the
// interleaved variant regressed gemm<2> by 38%).
// c in [0,6): hi*hi;  [6,12): a_hi*w_lo;  [12,18): a_lo*w_hi
__device__ __forceinline__ void chunk_offsets(int c, int& aoff, int& boff) {
    if (c < 6)       { aoff = c * 64;              boff = c * 64; }
    else if (c < 12) { aoff = (c - 6) * 64;        boff = 384 + (c - 6) * 64; }
    else             { aoff = 384 + (c - 12) * 64; boff = (c - 12) * 64; }
}

// base-4 digit reversal of a 12-bit index
__device__ __forceinline__ int rev4(unsigned n) {
    unsigned r2 = __brev(n) >> 20;
    return (int)(((r2 & 0x555u) << 1) | ((r2 >> 1) & 0x555u));
}

// ============================================================================
// Radix-4 FFT-4096 core: 4 complex columns (float2), 6 stages, twiddle table.
// ============================================================================
template <int DIR>   // -1 forward, +1 inverse
static __device__ __forceinline__ void fft4_core(float2* s, float2* tw, int tid) {
    {
        int off = 0, q = 1;
        #pragma unroll
        for (int st = 0; st < 6; st++) {
            for (int p = tid; p < q; p += FFT_THREADS) {
                float sn, cs;
                __sincosf(-6.283185307179586f * (float)p / (float)(4 * q), &sn, &cs);
                tw[off + p] = make_float2(cs, sn);
            }
            off += q; q <<= 2;
        }
    }
    __syncthreads();

    int off = 0, q = 1;
    #pragma unroll
    for (int st = 0; st < 6; st++) {
        for (int it = tid; it < 4 * (N_DIM / 4); it += FFT_THREADS) {
            const int col = it >> 10;
            const int j   = it & (N_DIM / 4 - 1);
            const int pos = j & (q - 1);
            float2* p0 = s + col * N_DIM + ((j - pos) << 2) + pos;

            float2 w1 = tw[off + pos];
            if (DIR > 0) w1.y = -w1.y;
            float2 w2 = cmul(w1, w1);
            float2 w3 = cmul(w2, w1);

            float2 a  = p0[0];
            float2 b  = cmul(p0[q],     w1);
            float2 c2 = cmul(p0[2 * q], w2);
            float2 d  = cmul(p0[3 * q], w3);

            float2 t0 = make_float2(a.x + c2.x, a.y + c2.y);
            float2 t1 = make_float2(a.x - c2.x, a.y - c2.y);
            float2 t2 = make_float2(b.x + d.x,  b.y + d.y);
            float2 t3 = make_float2(b.x - d.x,  b.y - d.y);
            float2 t3r = (DIR < 0) ? make_float2(t3.y, -t3.x)
                                   : make_float2(-t3.y, t3.x);

            p0[0]     = make_float2(t0.x + t2.x,  t0.y + t2.y);
            p0[q]     = make_float2(t1.x + t3r.x, t1.y + t3r.y);
            p0[2 * q] = make_float2(t0.x - t2.x,  t0.y - t2.y);
            p0[3 * q] = make_float2(t1.x - t3r.x, t1.y - t3r.y);
        }
        __syncthreads();
        off += q; q <<= 2;
    }
}

// ============================================================================
// K1 (FUSED): fwd FFT-4096 + paired-real unpack + FFT-4 across blocks
//   + 1/128 scale + bf16 hi/lo split + K-major A write (coalesced: fixed k,
//   consecutive m across threads).
// CTA = (b, dp): complex col j = x[:, j*192+2dp] + i * x[:, j*192+2dp+1].
// ============================================================================
__global__ __launch_bounds__(FFT_THREADS, 1) void fft_fwd_pack(const float* __restrict__ x) {
    extern __shared__ float2 smc[];
    float2* tw = smc + 4 * N_DIM;
    const int b  = blockIdx.x / 96;
    const int dp = blockIdx.x % 96;
    const int d  = 2 * dp;
    const int tid = threadIdx.x;

    for (int n = tid; n < N_DIM; n += FFT_THREADS) {
        const float* row = &x[((size_t)(b * N_DIM + n)) * C_DIM + d];
        int r = rev4((unsigned)n);
        smc[0 * N_DIM + r] = *(const float2*)(row);
        smc[1 * N_DIM + r] = *(const float2*)(row + BS);
        smc[2 * N_DIM + r] = *(const float2*)(row + 2 * BS);
        smc[3 * N_DIM + r] = *(const float2*)(row + 3 * BS);
    }
    fft4_core<-1>(smc, tw, tid);

    const size_t PLX = (size_t)GK * M_TOT;
    for (int k = tid; k < N_DIM; k += FFT_THREADS) {
        const int kr = (N_DIM - k) & (N_DIM - 1);
        float ar[4], ai[4], cr[4], ci[4];
        #pragma unroll
        for (int j = 0; j < 4; j++) {
            float2 P = smc[j * N_DIM + k];
            float2 Q = smc[j * N_DIM + kr];
            ar[j] = 0.5f * (P.x + Q.x);
            ai[j] = 0.5f * (P.y - Q.y);
            cr[j] = 0.5f * (P.y + Q.y);
            ci[j] = 0.5f * (Q.x - P.x);
        }
        const size_t m = (size_t)b * N_DIM + k;
        #pragma unroll
        for (int ch = 0; ch < 2; ch++) {
            const float* xr = ch ? cr : ar;
            const float* xi = ch ? ci : ai;
            float yr[4], yi[4];
            yr[0] = (xr[0] + xr[1] + xr[2] + xr[3]) * INV128;
            yi[0] = (xi[0] + xi[1] + xi[2] + xi[3]) * INV128;
            yr[1] = (xr[0] + xi[1] - xr[2] - xi[3]) * INV128;
            yi[1] = (xi[0] - xr[1] - xi[2] + xr[3]) * INV128;
            yr[2] = (xr[0] - xr[1] + xr[2] - xr[3]) * INV128;
            yi[2] = (xi[0] - xi[1] + xi[2] - xi[3]) * INV128;
            yr[3] = (xr[0] - xi[1] - xr[2] + xi[3]) * INV128;
            yi[3] = (xi[0] + xr[1] - xi[2] - xr[3]) * INV128;
            const int dd = d + ch;
            #pragma unroll
            for (int p = 0; p < 4; p++) {
                unsigned short* pl = g_XbT + p * PLX;
                __nv_bfloat16 hr = __float2bfloat16(yr[p]);
                __nv_bfloat16 hy = __float2bfloat16(yi[p]);
                pl[(size_t)(dd)           * M_TOT + m] = __bfloat16_as_ushort(hr);
                pl[(size_t)(BS + dd)      * M_TOT + m] = __bfloat16_as_ushort(hy);
                pl[(size_t)(KS + dd)      * M_TOT + m] =
                    __bfloat16_as_ushort(__float2bfloat16(yr[p] - __bfloat162float(hr)));
                pl[(size_t)(KS + BS + dd) * M_TOT + m] =
                    __bfloat16_as_ushort(__float2bfloat16(yi[p] - __bfloat162float(hy)));
            }
        }
    }
}

// ============================================================================
// K3: stacked weights, transposed + bf16 hi/lo.  Ws = [[Wr, Wi], [-Wi, Wr]]
// ============================================================================
__global__ void prep_weights(const float* __restrict__ w1, const float* __restrict__ b1,
                             const float* __restrict__ w2, const float* __restrict__ b2) {
    int idx = blockIdx.x * blockDim.x + threadIdx.x;
    if (idx < NB * KS * GK) {
        int k   = idx % GK;
        int n   = (idx / GK) % KS;
        int blk = idx / (GK * KS);
        int kk  = (k >= KS) ? k - KS : k;
        bool lohalf = (k >= KS);
        int dd = (kk < BS) ? kk : kk - BS;
        int cc = (n  < BS) ? n  : n  - BS;
        bool rlo = kk < BS, clo = n < BS;
        size_t ir = ((size_t)blk        * BS + dd) * BS + cc;
        size_t ii = ((size_t)(NB + blk) * BS + dd) * BS + cc;
        float v1, v2;
        if (rlo == clo) { v1 =  w1[ir]; v2 =  w2[ir]; }
        else if (rlo)   { v1 =  w1[ii]; v2 =  w2[ii]; }
        else            { v1 = -w1[ii]; v2 = -w2[ii]; }
        __nv_bfloat16 h1 = __float2bfloat16(v1);
        __nv_bfloat16 h2 = __float2bfloat16(v2);
        if (lohalf) {
            g_W1b[idx] = __bfloat16_as_ushort(__float2bfloat16(v1 - __bfloat162float(h1)));
            g_W2b[idx] = __bfloat16_as_ushort(__float2bfloat16(v2 - __bfloat162float(h2)));
        } else {
            g_W1b[idx] = __bfloat16_as_ushort(h1);
            g_W2b[idx] = __bfloat16_as_ushort(h2);
        }
    }
    if (idx < NB * KS) {
        int blk = idx / KS;
        int c   = idx % KS;
        size_t ib = (c < BS) ? ((size_t)blk * BS + c)
                             : ((size_t)(NB + blk) * BS + (c - BS));
        g_B1[idx] = b1[ib];
        g_B2[idx] = b2[ib];
    }
}

// ============================================================================
// K4/K5: HMMA bf16x3 GEMM. CTA 128x128, 8 warps (4x2), warp tile 32x64.
// 3-stage cp.async pipeline, 2 CTAs/SM, sequential chunk order (R10).
// LAYER 1: A K-major (g_XbT) -> 256B k-rows, (k&7)<<4 swizzle, trans-ldsm
//          (numerically validated in R11).
// LAYER 2: A m-major (g_Hb) -> SW128 rows, non-trans ldsm (proven path).
// ============================================================================
template <int LAYER>
__global__ __launch_bounds__(256, 2) void gemm_mma() {
    extern __shared__ __align__(1024) char smem_raw[];
    const uint32_t smem = smem_u32(smem_raw);
    const int tid    = threadIdx.x;
    const int wid    = tid >> 5;
    const int lane   = tid & 31;
    const int warp_m = wid & 3;
    const int warp_n = wid >> 2;
    const int n0     = blockIdx.x * 128;
    const int tile_m = blockIdx.y * 128;
    const int blk    = blockIdx.z;

    const unsigned short* A = (LAYER == 1)
        ? g_XbT + (size_t)blk * GK * M_TOT + tile_m
        : g_Hb  + (size_t)blk * M_TOT * GK + (size_t)tile_m * GK;
    const unsigned short* W = (LAYER == 1 ? g_W1b : g_W2b)
                            + (size_t)blk * KS * GK + (size_t)n0 * GK;
    const float* bias       = (LAYER == 1 ? g_B1 : g_B2) + blk * KS;

    float acc[2][8][4];
    #pragma unroll
    for (int i = 0; i < 2; i++)
        #pragma unroll
        for (int j = 0; j < 8; j++)
            #pragma unroll
            for (int q = 0; q < 4; q++) acc[i][j][q] = 0.f;

    auto load_chunk = [&](int c) {
        int aoff, boff; chunk_offsets(c, aoff, boff);
        uint32_t sA = smem + (c % NSTG) * STAGE_BYTES;
        uint32_t sB = sA + 16384;
        if (LAYER == 1) {
            // A chunk: 64 k-rows x 128 m (256B/row); swizzle m-slot ^ (k&7)
            #pragma unroll
            for (int t = 0; t < 4; t++) {
                int idx = tid + t * 256;
                int kl = idx >> 4, i = idx & 15;
                cp16(sA + (uint32_t)(kl * 256 + ((i * 16) ^ ((kl & 7) << 4))),
                     A + (size_t)(aoff + kl) * M_TOT + i * 8);
            }
        } else {
            #pragma unroll
            for (int t = 0; t < 4; t++) {
                int idx = tid + t * 256;
                int r = idx >> 3, i = idx & 7;
                cp16(sA + swz128((uint32_t)(r * 128 + i * 16)),
                     A + (size_t)r * GK + aoff + i * 8);
            }
        }
        #pragma unroll
        for (int t = 0; t < 4; t++) {
            int idx = tid + t * 256;
            int r = idx >> 3, i = idx & 7;
            cp16(sB + swz128((uint32_t)(r * 128 + i * 16)),
                 W + (size_t)r * GK + boff + i * 8);
        }
        asm volatile("cp.async.commit_group;" ::: "memory");
    };

    load_chunk(0);
    load_chunk(1);

    // non-trans A lane offsets (layer 2)
    const uint32_t a_row = (uint32_t)(warp_m * 32 + (lane & 15));
    const uint32_t a_cb  = (uint32_t)((lane >> 4) * 16);
    // trans A lane offsets (layer 1)
    const uint32_t a_kk_l = (uint32_t)((lane & 7) | ((lane >> 1) & 8));
    const uint32_t a_mb   = (uint32_t)(warp_m * 64 + (lane & 8) * 2);
    // B lane offsets
    const uint32_t b_row = (uint32_t)(warp_n * 64 + (lane & 7) + ((lane >> 4) * 8));
    const uint32_t b_cb  = (uint32_t)(((lane >> 3) & 1) * 16);

    for (int c = 0; c < KCH; c++) {
        if (c + 1 < KCH) asm volatile("cp.async.wait_group 1;" ::: "memory");
        else             asm volatile("cp.async.wait_group 0;" ::: "memory");
        __syncthreads();

        if (c + 2 < KCH) load_chunk(c + 2);

        const uint32_t sA = smem + (c % NSTG) * STAGE_BYTES;
        const uint32_t sB = sA + 16384;

        #pragma unroll
        for (int k16 = 0; k16 < 4; k16++) {
            uint32_t af[2][4], bf[4][4];
            if (LAYER == 1) {
                const uint32_t kkt = (uint32_t)(k16 * 16) + a_kk_l;
                const uint32_t sw  = (kkt & 7) << 4;
                #pragma unroll
                for (int mi = 0; mi < 2; mi++)
                    ldsm_x4_t(af[mi], sA + kkt * 256 + ((a_mb + mi * 32) ^ sw));
            } else {
                #pragma unroll
                for (int mi = 0; mi < 2; mi++)
                    ldsm_x4(af[mi], sA + swz128((a_row + mi * 16) * 128 + k16 * 32 + a_cb));
            }
            #pragma unroll
            for (int nj = 0; nj < 4; nj++)
                ldsm_x4(bf[nj], sB + swz128((b_row + nj * 16) * 128 + k16 * 32 + b_cb));
            #pragma unroll
            for (int mi = 0; mi < 2; mi++)
                #pragma unroll
                for (int nj = 0; nj < 4; nj++) {
                    mma16816(acc[mi][2 * nj],     af[mi], bf[nj][0], bf[nj][1]);
                    mma16816(acc[mi][2 * nj + 1], af[mi], bf[nj][2], bf[nj][3]);
                }
        }
    }

    // epilogue
    #pragma unroll
    for (int mi = 0; mi < 2; mi++) {
        #pragma unroll
        for (int na = 0; na < 8; na++) {
            const int col  = n0 + warp_n * 64 + na * 8 + 2 * (lane & 3);
            const int row0 = tile_m + warp_m * 32 + mi * 16 + (lane >> 2);
            const float b0 = bias[col], b1 = bias[col + 1];
            #pragma unroll
            for (int h = 0; h < 2; h++) {
                const int row = row0 + h * 8;
                float v0 = acc[mi][na][2 * h]     + b0;
                float v1 = acc[mi][na][2 * h + 1] + b1;
                if (LAYER == 1) {
                    v0 = fmaxf(v0, 0.f);
                    v1 = fmaxf(v1, 0.f);
                    __nv_bfloat16 h0 = __float2bfloat16(v0);
                    __nv_bfloat16 h1 = __float2bfloat16(v1);
                    ushort2 hs = make_ushort2(__bfloat16_as_ushort(h0),
                                              __bfloat16_as_ushort(h1));
                    ushort2 ls = make_ushort2(
                        __bfloat16_as_ushort(__float2bfloat16(v0 - __bfloat162float(h0))),
                        __bfloat16_as_ushort(__float2bfloat16(v1 - __bfloat162float(h1))));
                    unsigned short* rb = g_Hb + ((size_t)blk * M_TOT + row) * GK;
                    *(ushort2*)(rb + col)      = hs;
                    *(ushort2*)(rb + KS + col) = ls;
                } else {
                    v0 = (v0 > LAMBDA) ? v0 - LAMBDA
                                       : ((v0 < -LAMBDA) ? v0 + LAMBDA : 0.f);
                    v1 = (v1 > LAMBDA) ? v1 - LAMBDA
                                       : ((v1 < -LAMBDA) ? v1 + LAMBDA : 0.f);
                    *(float2*)(g_P + ((size_t)blk * M_TOT + row) * KS + col)
                        = make_float2(v0, v1);
                }
            }
        }
    }
}

// ============================================================================
// K6: inverse FFT-4 along block axis + hermitian channel-pair packing (R10).
// ============================================================================
__global__ void ifft4_wpack() {
    const int idx = blockIdx.x * blockDim.x + threadIdx.x;
    const int total = B_DIM * 2049 * 96;
    if (idx >= total) return;
    const int dp   = idx % 96;
    const int kpos = (idx / 96) % 2049;
    const int b    = idx / (96 * 2049);
    const int d    = 2 * dp;
    const int m1   = b * N_DIM + kpos;
    const int m2   = b * N_DIM + ((N_DIM - kpos) & (N_DIM - 1));

    const size_t PL = (size_t)M_TOT * KS;

    float z1r[4], z1i[4], z2r[4], z2i[4];
    #pragma unroll
    for (int rowsel = 0; rowsel < 2; rowsel++) {
        const int m = rowsel ? m2 : m1;
        float yrA[4], yiA[4], yrB[4], yiB[4];
        #pragma unroll
        for (int k2 = 0; k2 < 4; k2++) {
            const float* pp = g_P + k2 * PL + (size_t)m * KS;
            float2 re = *(const float2*)(pp + d);
            float2 im = *(const float2*)(pp + BS + d);
            yrA[k2] = re.x;  yrB[k2] = re.y;
            yiA[k2] = im.x;  yiB[k2] = im.y;
        }
        float zrA[4], ziA[4], zrB[4], ziB[4];
        zrA[0] = yrA[0] + yrA[1] + yrA[2] + yrA[3];
        ziA[0] = yiA[0] + yiA[1] + yiA[2] + yiA[3];
        zrA[1] = yrA[0] - yiA[1] - yrA[2] + yiA[3];
        ziA[1] = yiA[0] + yrA[1] - yiA[2] - yrA[3];
        zrA[2] = yrA[0] - yrA[1] + yrA[2] - yrA[3];
        ziA[2] = yiA[0] - yiA[1] + yiA[2] - yiA[3];
        zrA[3] = yrA[0] + yiA[1] - yrA[2] - yiA[3];
        ziA[3] = yiA[0] - yrA[1] - yiA[2] + yrA[3];
        zrB[0] = yrB[0] + yrB[1] + yrB[2] + yrB[3];
        ziB[0] = yiB[0] + yiB[1] + yiB[2] + yiB[3];
        zrB[1] = yrB[0] - yiB[1] - yrB[2] + yiB[3];
        ziB[1] = yiB[0] + yrB[1] - yiB[2] - yrB[3];
        zrB[2] = yrB[0] - yrB[1] + yrB[2] - yrB[3];
        ziB[2] = yiB[0] - yiB[1] + yiB[2] - yiB[3];
        zrB[3] = yrB[0] + yiB[1] - yrB[2] - yiB[3];
        ziB[3] = yiB[0] - yrB[1] - yiB[2] + yrB[3];
        if (rowsel == 0) {
            #pragma unroll
            for (int j = 0; j < 4; j++) {
                z1r[j] = zrA[j]; z1i[j] = ziA[j];
                z2r[j] = zrB[j]; z2i[j] = ziB[j];
            }
        } else {
            #pragma unroll
            for (int j = 0; j < 4; j++) {
                float v1r = 0.5f * (z1r[j] + zrA[j]);
                float v1i = 0.5f * (z1i[j] - ziA[j]);
                float v2r = 0.5f * (z2r[j] + zrB[j]);
                float v2i = 0.5f * (z2i[j] - ziB[j]);
                g_Wc[((size_t)j * M_TOT + m1) * 96 + dp] =
                    make_float2(v1r - v2i, v1i + v2r);
                g_Wc[((size_t)j * M_TOT + m2) * 96 + dp] =
                    make_float2(v1r + v2i, -v1i + v2r);
            }
        }
    }
}

// ============================================================================
// K7: inverse FFT-4096 on packed hermitian columns (radix-4); outputs real.
// ============================================================================
__global__ __launch_bounds__(FFT_THREADS, 1) void fft_n_inv(float* __restrict__ out) {
    extern __shared__ float2 smc[];
    float2* tw = smc + 4 * N_DIM;
    const int b   = blockIdx.x / 96;
    const int r8  = blockIdx.x % 96;
    const int blk = r8 / 24;
    const int dp0 = (r8 % 24) * 4;
    const int tid = threadIdx.x;

    for (int k = tid; k < N_DIM; k += FFT_THREADS) {
        const float2* wp = g_Wc + ((size_t)blk * M_TOT + b * N_DIM + k) * 96 + dp0;
        float2 w0 = wp[0], w1 = wp[1], w2 = wp[2], w3 = wp[3];
        int r = rev4((unsigned)k);
        smc[0 * N_DIM + r] = w0;
        smc[1 * N_DIM + r] = w1;
        smc[2 * N_DIM + r] = w2;
        smc[3 * N_DIM + r] = w3;
    }
    fft4_core<+1>(smc, tw, tid);

    const int cbase = blk * BS + 2 * dp0;
    for (int n = tid; n < N_DIM; n += FFT_THREADS) {
        float2 c0 = smc[n],             c1 = smc[N_DIM + n];
        float2 c2 = smc[2 * N_DIM + n], c3 = smc[3 * N_DIM + n];
        float4 o0 = make_float4(c0.x * INV128, c0.y * INV128,
                                c1.x * INV128, c1.y * INV128);
        float4 o1 = make_float4(c2.x * INV128, c2.y * INV128,
                                c3.x * INV128, c3.y * INV128);
        float* op = &out[((size_t)(b * N_DIM + n)) * C_DIM + cbase];
        *(float4*)op       = o0;
        *(float4*)(op + 4) = o1;
    }
}

// ============================================================================
// launch
// ============================================================================
extern "C" void kernel_launch(void* const* d_in, const int* in_sizes, int n_in,
                              void* d_out, int out_size) {
    (void)in_sizes; (void)n_in; (void)out_size;
    const float* x  = (const float*)d_in[0];
    const float* w1 = (const float*)d_in[1];
    const float* b1 = (const float*)d_in[2];
    const float* w2 = (const float*)d_in[3];
    const float* b2 = (const float*)d_in[4];
    float* out = (float*)d_out;

    cudaFuncSetAttribute(fft_fwd_pack, cudaFuncAttributeMaxDynamicSharedMemorySize, FFT_SMEM);
    cudaFuncSetAttribute(fft_n_inv,    cudaFuncAttributeMaxDynamicSharedMemorySize, FFT_SMEM);
    cudaFuncSetAttribute(gemm_mma<1>,  cudaFuncAttributeMaxDynamicSharedMemorySize, GEMM_SMEM);
    cudaFuncSetAttribute(gemm_mma<2>,  cudaFuncAttributeMaxDynamicSharedMemorySize, GEMM_SMEM);

    fft_fwd_pack<<<B_DIM * 96, FFT_THREADS, FFT_SMEM>>>(x);
    prep_weights<<<(NB * KS * GK + 255) / 256, 256>>>(w1, b1, w2, b2);

    dim3 gg(3, M_TOT / 128, NB);
    gemm_mma<1><<<gg, 256, GEMM_SMEM>>>();
    gemm_mma<2><<<gg, 256, GEMM_SMEM>>>();

    ifft4_wpack<<<(B_DIM * 2049 * 96 + 255) / 256, 256>>>();
    fft_n_inv<<<B_DIM * 96, FFT_THREADS, FFT_SMEM>>>(out);
}